// round 9
// baseline (speedup 1.0000x reference)
#include <cuda_runtime.h>
#include <cuda_bf16.h>
#include <cstdint>

// Single-kernel version. Hot mini-table (6 rows, 3KB) built per-block in smem:
//   rows 0..4 : C[c] = W[65] + W[131] + W[133+c]   (diff chain, ~98.4% of pairs)
//   row  5    : W[132]                             (entity row, kept in registers)
// Rare same-chain pairs (~1.6%) compute W[var]+W[fix]+W[138] directly from W
// (3x LDG.128, L1-hot, warp-uniform branch: the whole warp shares one j).
// jidx encoding: bit17 = same-chain, bit16 = entity,
//   same-chain:  bits0-7 = var row, bits8-15 = fix row (131 or 32)
//   diff-chain:  bits0-7 = hot row (0..4)

#define F_ENT  (1 << 16)
#define F_SAME (1 << 17)

__global__ void __launch_bounds__(256, 8)
rpe_main(const float* __restrict__ feats, const float* __restrict__ W,
         float* __restrict__ out, int n)
{
    __shared__ int jidx[1024];
    __shared__ __align__(16) float S[6 * 128];   // hot mini-table

    const int tid = threadIdx.x;
    const int i   = blockIdx.x;

    // ---- Phase 0: build 6-row hot table (768 floats) ----
    for (int idx = tid; idx < 6 * 128; idx += 256) {
        const int r = idx >> 7;
        const int e = idx & 127;
        float v;
        if (r < 5) v = W[65 * 128 + e] + W[131 * 128 + e] + W[(133 + r) * 128 + e];
        else       v = W[132 * 128 + e];
        S[idx] = v;
    }

    // ---- Phase A: per-j packed index ----
    const float res_i  = feats[i * 10 + 0];
    const float tok_i  = feats[i * 10 + 1];
    const float asym_i = feats[i * 10 + 2];
    const float ent_i  = feats[i * 10 + 3];
    const float sym_i  = feats[i * 10 + 4];

    for (int j = tid; j < n; j += 256) {
        const float res_j  = feats[j * 10 + 0];
        const float tok_j  = feats[j * 10 + 1];
        const float asym_j = feats[j * 10 + 2];
        const float ent_j  = feats[j * 10 + 3];
        const float sym_j  = feats[j * 10 + 4];

        int p;
        if (asym_i == asym_j) {
            const int dres = (int)(res_i - res_j);
            if (dres != 0) {
                // W[clip(dres+32)] + W[131] + W[138]
                p = F_SAME | min(max(dres + 32, 0), 64) | (131 << 8);
            } else {
                // W[66 + clip(dtok+32)] + W[32] + W[138]
                const int dtok = (int)(tok_i - tok_j);
                p = F_SAME | (66 + min(max(dtok + 32, 0), 64)) | (32 << 8);
            }
        } else {
            p = min(max((int)(sym_i - sym_j) + 2, 0), 4);      // hot C row
        }
        if (ent_i == ent_j) p |= F_ENT;
        jidx[j] = p;
    }
    __syncthreads();

    // ---- Phase B: warp-per-pair, hot-row LDS + streaming STG ----
    const int e4    = tid & 31;                  // float4 lane within 128-dim row
    const int wid   = tid >> 5;
    const int warps = 8;
    const float4* __restrict__ S4 = (const float4*)S;
    const float4* __restrict__ W4 = (const float4*)W;

    const float4 went  = S4[5 * 32 + e4];        // entity row in registers
    const float4 w138  = __ldg(&W4[138 * 32 + e4]);  // shared by all rare pairs

    float* __restrict__ out_i = out + ((size_t)i * (size_t)n) * 128;

    auto fetch = [&](int p) -> float4 {
        float4 v;
        if (!(p & F_SAME)) {                     // 98.4%, warp-uniform branch
            v = S4[(p & 7) * 32 + e4];
        } else {
            const float4 a = __ldg(&W4[(p & 255) * 32 + e4]);
            const float4 b = __ldg(&W4[((p >> 8) & 255) * 32 + e4]);
            v.x = a.x + b.x + w138.x;
            v.y = a.y + b.y + w138.y;
            v.z = a.z + b.z + w138.z;
            v.w = a.w + b.w + w138.w;
        }
        if (p & F_ENT) { v.x += went.x; v.y += went.y; v.z += went.z; v.w += went.w; }
        return v;
    };

    int j = wid;
    for (; j + warps < n; j += 2 * warps) {
        const int j2 = j + warps;
        const int p0 = jidx[j];
        const int p1 = jidx[j2];
        const float4 v0 = fetch(p0);
        const float4 v1 = fetch(p1);
        __stcs((float4*)(out_i + (size_t)j  * 128) + e4, v0);
        __stcs((float4*)(out_i + (size_t)j2 * 128) + e4, v1);
    }
    for (; j < n; j += warps) {
        const float4 v = fetch(jidx[j]);
        __stcs((float4*)(out_i + (size_t)j * 128) + e4, v);
    }
}

extern "C" void kernel_launch(void* const* d_in, const int* in_sizes, int n_in,
                              void* d_out, int out_size)
{
    const float* feats = (const float*)d_in[0];   // [1, n, 10] f32
    const float* W     = (const float*)d_in[1];   // [139, 128] f32
    float* out         = (float*)d_out;           // [1, n, n, 128] f32

    const int n = in_sizes[0] / 10;               // b == 1 (n == 1024)

    rpe_main<<<n, 256>>>(feats, W, out, n);
}